// round 15
// baseline (speedup 1.0000x reference)
#include <cuda_runtime.h>
#include <cuda_bf16.h>
#include <cstdint>

#define N_CELLS 50000
#define DEG 32
#define D 64
#define NEG_SLOPE 0.2f
#define ROWS_CTA 64
#define XPAD 68   // padded row stride (floats): 272B/row -> 16B aligned rows

typedef unsigned long long u64;

// ---- packed f32x2 helpers (lane-wise .rn == scalar ops, bit-exact) ----
__device__ __forceinline__ u64 packdup(float v) {
    u64 r; asm("mov.b64 %0, {%1, %1};" : "=l"(r) : "f"(v)); return r;
}
__device__ __forceinline__ void unpack2(u64 v, float& a, float& b) {
    asm("mov.b64 {%0, %1}, %2;" : "=f"(a), "=f"(b) : "l"(v));
}
__device__ __forceinline__ u64 fma2(u64 a, u64 b, u64 c) {
    u64 r; asm("fma.rn.f32x2 %0, %1, %2, %3;" : "=l"(r) : "l"(a), "l"(b), "l"(c)); return r;
}
__device__ __forceinline__ u64 mul2(u64 a, u64 b) {
    u64 r; asm("mul.rn.f32x2 %0, %1, %2;" : "=l"(r) : "l"(a), "l"(b)); return r;
}
__device__ __forceinline__ u64 add2(u64 a, u64 b) {
    u64 r; asm("add.rn.f32x2 %0, %1, %2;" : "=l"(r) : "l"(a), "l"(b)); return r;
}

// -------- Kernel 1: 2 threads per row (half-row each = 16 packed accs).
// 64 rows per 128-thread CTA -> 2x total warps vs thread-per-row (latency hiding).
// Bit-exact orders (validated R9/R12/R13):
//   gemm: per output column, sequential fused FMA over k=0..63 (f32x2 lanes;
//         each column's chain lives entirely in one thread)
//   gemv: width-8 strided fma partials over ascending col-pairs, AddReduce
//         halving ((p0+p4)+(p2+p6)) + ((p1+p5)+(p3+p7)) — done by one thread
//         per row on the staged acc values (identical bits to R13)
__global__ void __launch_bounds__(128) gemm_proj_kernel(
    const float* __restrict__ x,     // [N, 64]
    const float* __restrict__ W,     // [64, 64]
    const float* __restrict__ a0,    // [128, 1]
    float* __restrict__ msg,         // [N, 64]
    float* __restrict__ ns,          // [N]
    float* __restrict__ nd,          // [N]
    int n)
{
    __shared__ __align__(16) float Wsh[D * D];          // 16 KB, row-major [k][j]
    __shared__ __align__(16) float ash[2 * D];
    __shared__ __align__(16) float xsh[ROWS_CTA * XPAD]; // x rows, then acc staging

    const int tid = threadIdx.x;
    const int base = blockIdx.x * ROWS_CTA;
    const int rows_here = min(ROWS_CTA, n - base);

    for (int i = tid; i < D * D; i += 128) Wsh[i] = W[i];
    if (tid < 2 * D) ash[tid] = a0[tid];
    for (int idx = tid; idx < rows_here * D; idx += 128) {
        xsh[(idx >> 6) * XPAD + (idx & 63)] = x[(size_t)base * D + idx];
    }
    __syncthreads();

    const int r = tid >> 1;          // row slot 0..63
    const int h = tid & 1;           // half: cols [h*32, h*32+32)
    const bool active = r < rows_here;

    u64 acc[16];
    if (active) {
#pragma unroll
        for (int m = 0; m < 16; m++) acc[m] = 0ull;

        const float* __restrict__ xrow = xsh + r * XPAD;
#pragma unroll
        for (int kc = 0; kc < 16; kc++) {
            const float4 xv = *(const float4*)(xrow + kc * 4);
            const float xk[4] = {xv.x, xv.y, xv.z, xv.w};
#pragma unroll
            for (int kk = 0; kk < 4; kk++) {
                const u64 xd = packdup(xk[kk]);
                const ulonglong2* __restrict__ wr =
                    (const ulonglong2*)(Wsh + (kc * 4 + kk) * D + h * 32);
#pragma unroll
                for (int m = 0; m < 8; m++) {
                    const ulonglong2 wv = wr[m];
                    acc[2 * m]     = fma2(xd, wv.x, acc[2 * m]);
                    acc[2 * m + 1] = fma2(xd, wv.y, acc[2 * m + 1]);
                }
            }
        }
    }
    __syncthreads();   // all xsh x-reads complete before overwrite

    // stage acc into xsh: global col-pair jp = h*16+m at float offset r*XPAD+2*jp
    if (active) {
        u64* __restrict__ stage = (u64*)xsh + r * (XPAD / 2) + h * 16;
#pragma unroll
        for (int m = 0; m < 16; m++) stage[m] = acc[m];
    }
    __syncthreads();

    // coalesced msg store (float4 sweep)
    {
        float4* __restrict__ dst4 = (float4*)(msg + (size_t)base * D);
        const int total4 = rows_here * (D / 4);
        for (int q = tid; q < total4; q += 128) {
            dst4[q] = *(const float4*)(xsh + (q >> 4) * XPAD + (q & 15) * 4);
        }
    }

    // gemv: one thread per row over staged full-row pairs, exact R9/R12 order
    if (tid < rows_here) {
        const u64* __restrict__ ms2 = (const u64*)xsh + tid * (XPAD / 2);
        const u64* __restrict__ as2 = (const u64*)ash;
        const u64* __restrict__ ad2 = (const u64*)(ash + D);
        u64 pps[4] = {0ull, 0ull, 0ull, 0ull};
        u64 ppd[4] = {0ull, 0ull, 0ull, 0ull};
#pragma unroll
        for (int jp = 0; jp < 32; jp++) {
            const u64 mv = ms2[jp];
            pps[jp & 3] = fma2(mv, as2[jp], pps[jp & 3]);
            ppd[jp & 3] = fma2(mv, ad2[jp], ppd[jp & 3]);
        }
        {
            const u64 q01 = add2(pps[0], pps[2]);
            const u64 q23 = add2(pps[1], pps[3]);
            const u64 rr  = add2(q01, q23);
            float lo, hi; unpack2(rr, lo, hi);
            ns[base + tid] = __fadd_rn(lo, hi);
        }
        {
            const u64 q01 = add2(ppd[0], ppd[2]);
            const u64 q23 = add2(ppd[1], ppd[3]);
            const u64 rr  = add2(q01, q23);
            float lo, hi; unpack2(rr, lo, hi);
            nd[base + tid] = __fadd_rn(lo, hi);
        }
    }
}

// -------- Kernel 2: per-row edge attention + gather-aggregate. One warp per row.
// At the practical LTS cap (~410MB of L2 gathers ≈ 36µs) — unchanged.
__global__ void __launch_bounds__(256) gat_aggregate_kernel(
    const float* __restrict__ msg,   // [N, 64]
    const float* __restrict__ ns,    // [N]
    const float* __restrict__ nd,    // [N]
    const int*   __restrict__ cols,  // [N*32]
    const float* __restrict__ nv,    // [N*32]
    float* __restrict__ out,         // [N, 64]
    int n)
{
    __shared__ float2 cw[8][DEG];    // per-warp staged {col, wgt}

    const int wid = threadIdx.x >> 5;
    const int lane = threadIdx.x & 31;
    const int row = blockIdx.x * 8 + wid;
    if (row >= n) return;

    const int eidx = row * DEG + lane;
    const int col = cols[eidx];

    float e = __fadd_rn(ns[row], __ldg(&nd[col]));
    e = (e >= 0.f) ? e : __fmul_rn(NEG_SLOPE, e);

    // row sum: strictly sequential in edge order
    float S = 0.f;
#pragma unroll
    for (int k = 0; k < DEG; k++)
        S = __fadd_rn(S, __shfl_sync(0xFFFFFFFFu, e, k));

    const float att = __fdiv_rn(e, S);
    const float wgt = __fmul_rn(nv[eidx], att);   // vals = nv * att

    cw[wid][lane] = make_float2(__int_as_float(col), wgt);
    __syncwarp();

    const u64* __restrict__ m2 = (const u64*)msg;  // packed col-pairs
    u64 acc = 0ull;
#pragma unroll
    for (int kb = 0; kb < DEG; kb += 8) {
        int c[8]; u64 w2[8];
#pragma unroll
        for (int i = 0; i < 8; i++) {
            const float2 t = cw[wid][kb + i];      // broadcast LDS.64
            c[i] = __float_as_int(t.x);
            w2[i] = packdup(t.y);
        }
        u64 m[8];
#pragma unroll
        for (int i = 0; i < 8; i++)
            m[i] = m2[(size_t)c[i] * (D / 2) + lane];
#pragma unroll
        for (int i = 0; i < 8; i++)
            acc = add2(acc, mul2(w2[i], m[i]));    // ascending edge order
    }
    float ax, ay; unpack2(acc, ax, ay);
    ax = fmaxf(ax, 0.f);
    ay = fmaxf(ay, 0.f);
    ((float2*)out)[(size_t)row * (D / 2) + lane] = make_float2(ax, ay);
}

// Scratch for intermediates (no cudaMalloc allowed)
__device__ float g_msg[N_CELLS * D];
__device__ float g_ns[N_CELLS];
__device__ float g_nd[N_CELLS];

extern "C" void kernel_launch(void* const* d_in, const int* in_sizes, int n_in,
                              void* d_out, int out_size) {
    const float* x    = (const float*)d_in[0];   // x_source [N,64]
    // d_in[1] = edge_rows (implicit: repeat(arange(N), 32)) — unused
    const int*   cols = (const int*)  d_in[2];   // edge_cols [N*32]
    const float* nv   = (const float*)d_in[3];   // neighborhood_values [N*32]
    const float* W0   = (const float*)d_in[4];   // [64,64]
    const float* a0   = (const float*)d_in[5];   // [128,1]
    float* out = (float*)d_out;

    float* msg; float* ns; float* nd;
    cudaGetSymbolAddress((void**)&msg, g_msg);
    cudaGetSymbolAddress((void**)&ns,  g_ns);
    cudaGetSymbolAddress((void**)&nd,  g_nd);

    const int n = N_CELLS;

    // Kernel 1: 64 rows per 128-thread CTA (2 threads/row)
    int grid1 = (n + ROWS_CTA - 1) / ROWS_CTA;
    gemm_proj_kernel<<<grid1, 128>>>(x, W0, a0, msg, ns, nd, n);

    // Kernel 2: one warp per row, 8 rows per 256-thread block
    int grid2 = (n + 7) / 8;
    gat_aggregate_kernel<<<grid2, 256>>>(msg, ns, nd, cols, nv, out, n);
}